// round 2
// baseline (speedup 1.0000x reference)
#include <cuda_runtime.h>

#define BATCH 4
#define C1N 128
#define C2N 64
#define NPIX1 16384   // 128*128
#define NPIX2 65536   // 256*256
#define NB 256

// ---- scratch (device globals; all fully overwritten every launch) ----
__device__ float g_gap1[BATCH * C1N];          // per-channel means of x1
__device__ float g_gap2[BATCH * C2N];          // per-channel means of x2
__device__ float g_pos1[BATCH * NB * 64];      // [b][n][ij]
__device__ float g_pos2[BATCH * NB * 256];     // [b][n][ij]
__device__ float g_spa [BATCH * NPIX2];        // [b][h=n][w=k]
__device__ float g_w3  [BATCH * C2N * C2N];    // A[o]*w_f[o][c]*cw[b][c]
__device__ float g_s3  [C2N];                  // A[o]*sum_c w_f[o][c]
__device__ float g_t3  [C2N];                  // A[o]*b_f[o] + beta[o]

__device__ __forceinline__ float warpSum(float v) {
    #pragma unroll
    for (int o = 16; o; o >>= 1) v += __shfl_xor_sync(0xffffffffu, v, o);
    return v;
}

// ---- kernel 1: per-channel means for x1 and x2 (one CTA per channel plane) ----
__global__ void k_gap(const float* __restrict__ x1, const float* __restrict__ x2) {
    __shared__ float sred[8];
    int id = blockIdx.x, tid = threadIdx.x;
    const float4* src; int n4; float* dst; float inv;
    if (id < BATCH * C1N) {
        src = (const float4*)(x1 + (size_t)id * NPIX1);
        n4 = NPIX1 / 4; dst = &g_gap1[id]; inv = 1.f / NPIX1;
    } else {
        int j = id - BATCH * C1N;
        src = (const float4*)(x2 + (size_t)j * NPIX2);
        n4 = NPIX2 / 4; dst = &g_gap2[j]; inv = 1.f / NPIX2;
    }
    float s = 0.f;
    for (int i = tid; i < n4; i += 256) {
        float4 v = src[i];
        s += (v.x + v.y) + (v.z + v.w);
    }
    s = warpSum(s);
    if ((tid & 31) == 0) sred[tid >> 5] = s;
    __syncthreads();
    if (tid == 0) {
        float t = 0.f;
        #pragma unroll
        for (int w = 0; w < 8; w++) t += sred[w];
        *dst = t * inv;
    }
}

// ---- kernel 2: pos1[b][n][ij] = sum_c w_p1[c]*x1[b,c,y,x] + b_p1 ----
__global__ void k_pos1(const float* __restrict__ x1,
                       const float* __restrict__ wp, const float* __restrict__ bp) {
    __shared__ float sw[C1N];
    int tid = threadIdx.x;
    if (tid < C1N) sw[tid] = wp[tid];
    __syncthreads();
    int b = blockIdx.x >> 6;
    int p = ((blockIdx.x & 63) << 8) | tid;         // pixel within batch plane
    const float* base = x1 + (size_t)b * C1N * NPIX1 + p;
    float d0 = 0.f, d1 = 0.f, d2 = 0.f, d3 = 0.f;
    #pragma unroll 4
    for (int c = 0; c < C1N; c += 4) {
        d0 += sw[c + 0] * base[(size_t)(c + 0) * NPIX1];
        d1 += sw[c + 1] * base[(size_t)(c + 1) * NPIX1];
        d2 += sw[c + 2] * base[(size_t)(c + 2) * NPIX1];
        d3 += sw[c + 3] * base[(size_t)(c + 3) * NPIX1];
    }
    float dot = ((d0 + d1) + (d2 + d3)) + bp[0];
    int y = p >> 7, x = p & 127;
    int n  = ((y >> 3) << 4) | (x >> 3);
    int ij = ((y & 7) << 3) | (x & 7);
    g_pos1[((b << 8) | n) * 64 + ij] = dot;
}

// ---- kernel 3: pos2[b][n][ij] = sum_c w_p2[c]*x2[b,c,y,x] + b_p2 ----
__global__ void k_pos2(const float* __restrict__ x2,
                       const float* __restrict__ wp, const float* __restrict__ bp) {
    __shared__ float sw[C2N];
    int tid = threadIdx.x;
    if (tid < C2N) sw[tid] = wp[tid];
    __syncthreads();
    int b = blockIdx.x >> 8;
    int p = ((blockIdx.x & 255) << 8) | tid;
    const float* base = x2 + (size_t)b * C2N * NPIX2 + p;
    float d0 = 0.f, d1 = 0.f, d2 = 0.f, d3 = 0.f;
    #pragma unroll 4
    for (int c = 0; c < C2N; c += 4) {
        d0 += sw[c + 0] * base[(size_t)(c + 0) << 16];
        d1 += sw[c + 1] * base[(size_t)(c + 1) << 16];
        d2 += sw[c + 2] * base[(size_t)(c + 2) << 16];
        d3 += sw[c + 3] * base[(size_t)(c + 3) << 16];
    }
    float dot = ((d0 + d1) + (d2 + d3)) + bp[0];
    int y = p >> 8, x = p & 255;
    int n  = ((y >> 4) << 4) | (x >> 4);
    int ij = ((y & 15) << 4) | (x & 15);
    g_pos2[((b << 8) | n) * 256 + ij] = dot;
}

// ---- kernel 4: tiny glue — mlp1/mlp2 -> cw softmax -> prefused w3/s3/t3 ----
__global__ void k_small(const float* __restrict__ wc1, const float* __restrict__ bc1,
                        const float* __restrict__ wc2, const float* __restrict__ bc2,
                        const float* __restrict__ wf,  const float* __restrict__ bf,
                        const float* __restrict__ gamma, const float* __restrict__ beta) {
    __shared__ float s_m1[256], s_m2[256], s_cw[256];
    int t = threadIdx.x;
    int b = t >> 6, g = (t >> 3) & 7, o = t & 7;
    // mlp1[b,g,o] = relu(sum_{c<16} w_c1[o,c]*gap1[b,g,c] + b_c1[o])
    {
        float a = bc1[o];
        const float* gp = &g_gap1[(b * 8 + g) * 16];
        #pragma unroll
        for (int c = 0; c < 16; c++) a += wc1[o * 16 + c] * gp[c];
        s_m1[t] = fmaxf(a, 0.f);
    }
    // mlp2[b,g,o]
    {
        float a = bc2[o];
        const float* gp = &g_gap2[(b * 8 + g) * 8];
        #pragma unroll
        for (int c = 0; c < 8; c++) a += wc2[o * 8 + c] * gp[c];
        s_m2[t] = fmaxf(a, 0.f);
    }
    __syncthreads();
    if (t < 32) {     // one thread per (b,g): softmax over 8 channels
        int bb = t >> 3, gg = t & 7;
        int base = bb * 64 + gg * 8;
        float nr = 0.f;
        #pragma unroll
        for (int j = 0; j < 8; j++) { float m = s_m2[base + j]; nr += m * m; }
        float lg[8]; float mx = -1e30f;
        #pragma unroll
        for (int j = 0; j < 8; j++) { lg[j] = s_m1[base + j] * nr; mx = fmaxf(mx, lg[j]); }
        float Z = 0.f;
        #pragma unroll
        for (int j = 0; j < 8; j++) { lg[j] = expf(lg[j] - mx); Z += lg[j]; }
        float iz = 1.f / Z;
        #pragma unroll
        for (int j = 0; j < 8; j++) s_cw[base + j] = lg[j] * iz;
    }
    __syncthreads();
    const float A = rsqrtf(1.f + 1e-5f);
    for (int i = t; i < BATCH * 64 * 64; i += 256) {
        int bb = i >> 12, oc = i & 4095, oo = oc >> 6, cc = oc & 63;
        g_w3[i] = gamma[oo] * A * wf[oc] * s_cw[bb * 64 + cc];
    }
    if (t < 64) {
        float ws = 0.f;
        for (int c = 0; c < 64; c++) ws += wf[t * 64 + c];
        float Ao = gamma[t] * A;
        g_s3[t] = Ao * ws;
        g_t3[t] = Ao * bf[t] + beta[t];
    }
}

// ---- kernel 5: per-block spatial attention (exp computed ONCE per (q,k)) ----
__global__ void __launch_bounds__(256) k_spa(const float* __restrict__ wlin,
                                             const float* __restrict__ blin) {
    __shared__ float s_p1[64], s_x1t[256], s_p2[256], s_red[18];
    __shared__ float s_acc[8 * 256];
    int tid = threadIdx.x, wid = tid >> 5, lane = tid & 31;
    int blk = blockIdx.x;                 // = b*256 + n
    if (tid < 64) s_p1[tid] = g_pos1[blk * 64 + tid];
    s_p2[tid] = g_pos2[blk * 256 + tid];
    __syncthreads();
    // x1t[k] = w_lin[k,:] . pos1 + b_lin[k]
    float acc_t = blin[tid];
    const float4* wr = (const float4*)(wlin + tid * 64);
    #pragma unroll
    for (int c4 = 0; c4 < 16; c4++) {
        float4 w = wr[c4];
        acc_t += w.x * s_p1[c4 * 4 + 0] + w.y * s_p1[c4 * 4 + 1]
               + w.z * s_p1[c4 * 4 + 2] + w.w * s_p1[c4 * 4 + 3];
    }
    s_x1t[tid] = acc_t;
    // block min/max of x1t (for stable exp)
    float vmax = acc_t, vmin = acc_t;
    #pragma unroll
    for (int o = 16; o; o >>= 1) {
        vmax = fmaxf(vmax, __shfl_xor_sync(0xffffffffu, vmax, o));
        vmin = fminf(vmin, __shfl_xor_sync(0xffffffffu, vmin, o));
    }
    if (lane == 0) { s_red[wid] = vmax; s_red[8 + wid] = vmin; }
    __syncthreads();
    if (tid == 0) {
        float mx = s_red[0], mn = s_red[8];
        #pragma unroll
        for (int w = 1; w < 8; w++) { mx = fmaxf(mx, s_red[w]); mn = fminf(mn, s_red[8 + w]); }
        s_red[16] = mx; s_red[17] = mn;
    }
    __syncthreads();
    float xmax = s_red[16], xmin = s_red[17];

    float accl[8];
    #pragma unroll
    for (int j = 0; j < 8; j++) accl[j] = 0.f;

    for (int q = wid; q < 256; q += 8) {       // warp owns row q
        float p = s_p2[q];
        float rm = (p >= 0.f) ? p * xmax : p * xmin;   // exact row max of scores
        float e[8]; float sum = 0.f;
        #pragma unroll
        for (int j = 0; j < 8; j++) {
            float v = __expf(fmaf(p, s_x1t[lane + 32 * j], -rm));
            e[j] = v; sum += v;
        }
        #pragma unroll
        for (int o = 16; o; o >>= 1) sum += __shfl_xor_sync(0xffffffffu, sum, o);
        float coef = p / sum;                  // weighted[k] += pos2[q]*e/Z
        #pragma unroll
        for (int j = 0; j < 8; j++) accl[j] += coef * e[j];
    }
    #pragma unroll
    for (int j = 0; j < 8; j++) s_acc[wid * 256 + lane + 32 * j] = accl[j];
    __syncthreads();
    float v = 0.f;
    #pragma unroll
    for (int w = 0; w < 8; w++) v += s_acc[w * 256 + tid];
    g_spa[blk * 256 + tid] = v;                // spa[b][h=n][w=k]
}

// ---- kernel 6: fused 1x1 conv (64->64) + BN + ReLU; one pixel per thread ----
__global__ void __launch_bounds__(256) k_fuse(const float* __restrict__ x2,
                                              float* __restrict__ out) {
    __shared__ float s_w[64 * 64];   // [c][o]
    __shared__ float s_s3[64], s_t3[64];
    int tid = threadIdx.x;
    int b = blockIdx.x >> 8;
    int p = ((blockIdx.x & 255) << 8) | tid;
    for (int i = tid; i < 4096; i += 256)        // transpose [o][c] -> [c][o]
        s_w[(i & 63) * 64 + (i >> 6)] = g_w3[b * 4096 + i];
    if (tid < 64) { s_s3[tid] = g_s3[tid]; s_t3[tid] = g_t3[tid]; }
    __syncthreads();

    float acc[64];
    #pragma unroll
    for (int o = 0; o < 64; o++) acc[o] = 0.f;

    const float* xb = x2 + (size_t)b * C2N * NPIX2 + p;
    for (int c = 0; c < 64; c++) {
        float xv = xb[(size_t)c << 16];
        const float4* wc = (const float4*)&s_w[c << 6];
        #pragma unroll
        for (int o4 = 0; o4 < 16; o4++) {
            float4 w = wc[o4];
            acc[o4 * 4 + 0] = fmaf(w.x, xv, acc[o4 * 4 + 0]);
            acc[o4 * 4 + 1] = fmaf(w.y, xv, acc[o4 * 4 + 1]);
            acc[o4 * 4 + 2] = fmaf(w.z, xv, acc[o4 * 4 + 2]);
            acc[o4 * 4 + 3] = fmaf(w.w, xv, acc[o4 * 4 + 3]);
        }
    }
    float sv = g_spa[(size_t)b * NPIX2 + p];
    float* ob = out + (size_t)b * C2N * NPIX2 + p;
    #pragma unroll
    for (int o = 0; o < 64; o++) {
        float r = fmaf(s_s3[o], sv, acc[o]) + s_t3[o];
        ob[(size_t)o << 16] = fmaxf(r, 0.f);
    }
}

extern "C" void kernel_launch(void* const* d_in, const int* in_sizes, int n_in,
                              void* d_out, int out_size) {
    const float* x1    = (const float*)d_in[0];
    const float* x2    = (const float*)d_in[1];
    const float* wc1   = (const float*)d_in[2];
    const float* bc1   = (const float*)d_in[3];
    const float* wc2   = (const float*)d_in[4];
    const float* bc2   = (const float*)d_in[5];
    const float* wp1   = (const float*)d_in[6];
    const float* bp1   = (const float*)d_in[7];
    const float* wp2   = (const float*)d_in[8];
    const float* bp2   = (const float*)d_in[9];
    const float* wlin  = (const float*)d_in[10];
    const float* blin  = (const float*)d_in[11];
    const float* wf    = (const float*)d_in[12];
    const float* bf    = (const float*)d_in[13];
    const float* gamma = (const float*)d_in[14];
    const float* beta  = (const float*)d_in[15];
    float* out = (float*)d_out;

    k_gap  <<<BATCH * C1N + BATCH * C2N, 256>>>(x1, x2);
    k_pos1 <<<BATCH * NPIX1 / 256, 256>>>(x1, wp1, bp1);
    k_pos2 <<<BATCH * NPIX2 / 256, 256>>>(x2, wp2, bp2);
    k_small<<<1, 256>>>(wc1, bc1, wc2, bc2, wf, bf, gamma, beta);
    k_spa  <<<BATCH * NB, 256>>>(wlin, blin);
    k_fuse <<<BATCH * NPIX2 / 256, 256>>>(x2, out);
}

// round 3
// speedup vs baseline: 1.1454x; 1.1454x over previous
#include <cuda_runtime.h>

#define BATCH 4
#define C1N 128
#define C2N 64
#define NPIX1 16384   // 128*128
#define NPIX2 65536   // 256*256
#define NB 256

// ---- scratch (device globals; zero-init at load; k_fuse re-zeroes g_gaps) ----
__device__ float g_gaps[BATCH * C1N + BATCH * C2N];  // [0,512): x1 sums, [512,768): x2 sums
__device__ float g_pos1[BATCH * NB * 64];            // [b][n][ij]
__device__ float g_pos2[BATCH * NB * 256];           // [b][n][ij]
__device__ float g_spa [BATCH * NPIX2];              // [b][h=n][w=k]
__device__ float g_w3t [BATCH * C2N * C2N];          // [b][c][o]  prefused, transposed
__device__ float g_s3  [C2N];
__device__ float g_t3  [C2N];

__device__ __forceinline__ float warpSum(float v) {
    #pragma unroll
    for (int o = 16; o; o >>= 1) v += __shfl_xor_sync(0xffffffffu, v, o);
    return v;
}

// ---- kernel 1: pos1 + x1 channel sums fused (reads x1 once) ----
__global__ void __launch_bounds__(256) k_pos1(const float* __restrict__ x1,
                                              const float* __restrict__ wp,
                                              const float* __restrict__ bp) {
    __shared__ float sw[C1N];
    __shared__ float spart[8 * C1N];
    int tid = threadIdx.x, wid = tid >> 5, lane = tid & 31;
    if (tid < C1N) sw[tid] = wp[tid];
    __syncthreads();
    int b = blockIdx.x >> 6;
    int p = ((blockIdx.x & 63) << 8) | tid;
    const float* base = x1 + (size_t)b * C1N * NPIX1 + p;
    float dot = 0.f;
    #pragma unroll 4
    for (int c = 0; c < C1N; c++) {
        float xv = base[(size_t)c << 14];
        dot = fmaf(sw[c], xv, dot);
        float r = warpSum(xv);
        if (lane == 0) spart[wid * C1N + c] = r;
    }
    dot += bp[0];
    int y = p >> 7, x = p & 127;
    int n  = ((y >> 3) << 4) | (x >> 3);
    int ij = ((y & 7) << 3) | (x & 7);
    g_pos1[((b << 8) | n) * 64 + ij] = dot;
    __syncthreads();
    if (tid < C1N) {
        float s = 0.f;
        #pragma unroll
        for (int w = 0; w < 8; w++) s += spart[w * C1N + tid];
        atomicAdd(&g_gaps[b * C1N + tid], s);
    }
}

// ---- kernel 2: pos2 + x2 channel sums fused (reads x2 once) ----
__global__ void __launch_bounds__(256) k_pos2(const float* __restrict__ x2,
                                              const float* __restrict__ wp,
                                              const float* __restrict__ bp) {
    __shared__ float sw[C2N];
    __shared__ float spart[8 * C2N];
    int tid = threadIdx.x, wid = tid >> 5, lane = tid & 31;
    if (tid < C2N) sw[tid] = wp[tid];
    __syncthreads();
    int b = blockIdx.x >> 8;
    int p = ((blockIdx.x & 255) << 8) | tid;
    const float* base = x2 + (size_t)b * C2N * NPIX2 + p;
    float dot = 0.f;
    #pragma unroll 4
    for (int c = 0; c < C2N; c++) {
        float xv = base[(size_t)c << 16];
        dot = fmaf(sw[c], xv, dot);
        float r = warpSum(xv);
        if (lane == 0) spart[wid * C2N + c] = r;
    }
    dot += bp[0];
    int y = p >> 8, x = p & 255;
    int n  = ((y >> 4) << 4) | (x >> 4);
    int ij = ((y & 15) << 4) | (x & 15);
    g_pos2[((b << 8) | n) * 256 + ij] = dot;
    __syncthreads();
    if (tid < C2N) {
        float s = 0.f;
        #pragma unroll
        for (int w = 0; w < 8; w++) s += spart[w * C2N + tid];
        atomicAdd(&g_gaps[BATCH * C1N + b * C2N + tid], s);
    }
}

// ---- kernel 3: mlp -> cw softmax (redundant per CTA) -> prefused w3t/s3/t3 ----
__global__ void __launch_bounds__(256) k_w3(const float* __restrict__ wc1, const float* __restrict__ bc1,
                                            const float* __restrict__ wc2, const float* __restrict__ bc2,
                                            const float* __restrict__ wf,  const float* __restrict__ bf,
                                            const float* __restrict__ gamma, const float* __restrict__ beta) {
    __shared__ float s_m1[256], s_m2[256], s_cw[256];
    int t = threadIdx.x;
    int b = t >> 6, g = (t >> 3) & 7, o = t & 7;
    const float INV1 = 1.f / NPIX1, INV2 = 1.f / NPIX2;
    {
        float a = bc1[o];
        const float* gp = &g_gaps[b * C1N + g * 16];
        #pragma unroll
        for (int c = 0; c < 16; c++) a = fmaf(wc1[o * 16 + c] * INV1, gp[c], a);
        s_m1[t] = fmaxf(a, 0.f);
    }
    {
        float a = bc2[o];
        const float* gp = &g_gaps[BATCH * C1N + b * C2N + g * 8];
        #pragma unroll
        for (int c = 0; c < 8; c++) a = fmaf(wc2[o * 8 + c] * INV2, gp[c], a);
        s_m2[t] = fmaxf(a, 0.f);
    }
    __syncthreads();
    if (t < 32) {
        int bb = t >> 3, gg = t & 7;
        int base = bb * 64 + gg * 8;
        float nr = 0.f;
        #pragma unroll
        for (int j = 0; j < 8; j++) { float m = s_m2[base + j]; nr += m * m; }
        float lg[8]; float mx = -1e30f;
        #pragma unroll
        for (int j = 0; j < 8; j++) { lg[j] = s_m1[base + j] * nr; mx = fmaxf(mx, lg[j]); }
        float Z = 0.f;
        #pragma unroll
        for (int j = 0; j < 8; j++) { lg[j] = expf(lg[j] - mx); Z += lg[j]; }
        float iz = 1.f / Z;
        #pragma unroll
        for (int j = 0; j < 8; j++) s_cw[base + j] = lg[j] * iz;
    }
    __syncthreads();
    const float A = rsqrtf(1.f + 1e-5f);
    #pragma unroll
    for (int k = 0; k < 4; k++) {            // this CTA's 1024-elem slice of [b][c][o]
        int i = blockIdx.x * 1024 + k * 256 + t;
        int bb = i >> 12, co = i & 4095, cc = co >> 6, oo = co & 63;
        g_w3t[i] = gamma[oo] * A * wf[oo * 64 + cc] * s_cw[bb * 64 + cc];
    }
    if (blockIdx.x == 0 && t < 64) {
        float ws = 0.f;
        for (int c = 0; c < 64; c++) ws += wf[t * 64 + c];
        float Ao = gamma[t] * A;
        g_s3[t] = Ao * ws;
        g_t3[t] = Ao * bf[t] + beta[t];
    }
}

// ---- kernel 4: per-block spatial attention (exp computed ONCE per (q,k)) ----
__global__ void __launch_bounds__(256) k_spa(const float* __restrict__ wlin,
                                             const float* __restrict__ blin) {
    __shared__ float s_p1[64], s_x1t[256], s_p2[256], s_red[18];
    __shared__ float s_acc[8 * 256];
    int tid = threadIdx.x, wid = tid >> 5, lane = tid & 31;
    int blk = blockIdx.x;                 // = b*256 + n
    if (tid < 64) s_p1[tid] = g_pos1[blk * 64 + tid];
    s_p2[tid] = g_pos2[blk * 256 + tid];
    __syncthreads();
    float acc_t = blin[tid];
    const float4* wr = (const float4*)(wlin + tid * 64);
    #pragma unroll
    for (int c4 = 0; c4 < 16; c4++) {
        float4 w = wr[c4];
        acc_t += w.x * s_p1[c4 * 4 + 0] + w.y * s_p1[c4 * 4 + 1]
               + w.z * s_p1[c4 * 4 + 2] + w.w * s_p1[c4 * 4 + 3];
    }
    s_x1t[tid] = acc_t;
    float vmax = acc_t, vmin = acc_t;
    #pragma unroll
    for (int o = 16; o; o >>= 1) {
        vmax = fmaxf(vmax, __shfl_xor_sync(0xffffffffu, vmax, o));
        vmin = fminf(vmin, __shfl_xor_sync(0xffffffffu, vmin, o));
    }
    if (lane == 0) { s_red[wid] = vmax; s_red[8 + wid] = vmin; }
    __syncthreads();
    if (tid == 0) {
        float mx = s_red[0], mn = s_red[8];
        #pragma unroll
        for (int w = 1; w < 8; w++) { mx = fmaxf(mx, s_red[w]); mn = fminf(mn, s_red[8 + w]); }
        s_red[16] = mx; s_red[17] = mn;
    }
    __syncthreads();
    float xmax = s_red[16], xmin = s_red[17];

    float accl[8];
    #pragma unroll
    for (int j = 0; j < 8; j++) accl[j] = 0.f;

    for (int q = wid; q < 256; q += 8) {
        float p = s_p2[q];
        float rm = (p >= 0.f) ? p * xmax : p * xmin;
        float e[8]; float sum = 0.f;
        #pragma unroll
        for (int j = 0; j < 8; j++) {
            float v = __expf(fmaf(p, s_x1t[lane + 32 * j], -rm));
            e[j] = v; sum += v;
        }
        #pragma unroll
        for (int o = 16; o; o >>= 1) sum += __shfl_xor_sync(0xffffffffu, sum, o);
        float coef = p / sum;
        #pragma unroll
        for (int j = 0; j < 8; j++) accl[j] += coef * e[j];
    }
    #pragma unroll
    for (int j = 0; j < 8; j++) s_acc[wid * 256 + lane + 32 * j] = accl[j];
    __syncthreads();
    float v = 0.f;
    #pragma unroll
    for (int w = 0; w < 8; w++) v += s_acc[w * 256 + tid];
    g_spa[blk * 256 + tid] = v;
}

// ---- kernel 5: fused 1x1 conv + BN + ReLU with packed f32x2 FMA ----
__global__ void __launch_bounds__(256) k_fuse(const float* __restrict__ x2,
                                              float* __restrict__ out) {
    __shared__ float s_w[C2N * C2N];   // [c][o] (g_w3t already transposed)
    __shared__ float s_s3[64], s_t3[64];
    int tid = threadIdx.x;
    int b = blockIdx.x >> 8;
    int p = ((blockIdx.x & 255) << 8) | tid;

    // re-zero the gap accumulators for the next graph replay (block 0 only)
    if (blockIdx.x == 0) {
        for (int i = tid; i < BATCH * C1N + BATCH * C2N; i += 256) g_gaps[i] = 0.f;
    }

    const float4* gw = (const float4*)&g_w3t[b * 4096];
    float4* swv = (float4*)s_w;
    for (int i = tid; i < 1024; i += 256) swv[i] = gw[i];
    if (tid < 64) { s_s3[tid] = g_s3[tid]; s_t3[tid] = g_t3[tid]; }
    __syncthreads();

    unsigned long long acc[32];
    #pragma unroll
    for (int j = 0; j < 32; j++) acc[j] = 0ull;

    const float* xb = x2 + (size_t)b * C2N * NPIX2 + p;
    for (int c = 0; c < 64; c++) {
        float xv = xb[(size_t)c << 16];
        unsigned long long xv2;
        asm("mov.b64 %0, {%1, %1};" : "=l"(xv2) : "f"(xv));
        const ulonglong2* wc = (const ulonglong2*)&s_w[c << 6];
        #pragma unroll
        for (int j = 0; j < 16; j++) {
            ulonglong2 w = wc[j];
            asm("fma.rn.f32x2 %0, %1, %2, %0;" : "+l"(acc[2 * j + 0]) : "l"(w.x), "l"(xv2));
            asm("fma.rn.f32x2 %0, %1, %2, %0;" : "+l"(acc[2 * j + 1]) : "l"(w.y), "l"(xv2));
        }
    }
    float sv = g_spa[(size_t)b * NPIX2 + p];
    float* ob = out + (size_t)b * C2N * NPIX2 + p;
    #pragma unroll
    for (int j = 0; j < 32; j++) {
        float lo, hi;
        asm("mov.b64 {%0, %1}, %2;" : "=f"(lo), "=f"(hi) : "l"(acc[j]));
        int o = 2 * j;
        float r0 = fmaf(s_s3[o + 0], sv, lo) + s_t3[o + 0];
        float r1 = fmaf(s_s3[o + 1], sv, hi) + s_t3[o + 1];
        ob[(size_t)(o + 0) << 16] = fmaxf(r0, 0.f);
        ob[(size_t)(o + 1) << 16] = fmaxf(r1, 0.f);
    }
}

extern "C" void kernel_launch(void* const* d_in, const int* in_sizes, int n_in,
                              void* d_out, int out_size) {
    const float* x1    = (const float*)d_in[0];
    const float* x2    = (const float*)d_in[1];
    const float* wc1   = (const float*)d_in[2];
    const float* bc1   = (const float*)d_in[3];
    const float* wc2   = (const float*)d_in[4];
    const float* bc2   = (const float*)d_in[5];
    const float* wp1   = (const float*)d_in[6];
    const float* bp1   = (const float*)d_in[7];
    const float* wp2   = (const float*)d_in[8];
    const float* bp2   = (const float*)d_in[9];
    const float* wlin  = (const float*)d_in[10];
    const float* blin  = (const float*)d_in[11];
    const float* wf    = (const float*)d_in[12];
    const float* bf    = (const float*)d_in[13];
    const float* gamma = (const float*)d_in[14];
    const float* beta  = (const float*)d_in[15];
    float* out = (float*)d_out;

    k_pos1<<<BATCH * NPIX1 / 256, 256>>>(x1, wp1, bp1);
    k_pos2<<<BATCH * NPIX2 / 256, 256>>>(x2, wp2, bp2);
    k_w3  <<<16, 256>>>(wc1, bc1, wc2, bc2, wf, bf, gamma, beta);
    k_spa <<<BATCH * NB, 256>>>(wlin, blin);
    k_fuse<<<BATCH * NPIX2 / 256, 256>>>(x2, out);
}